// round 13
// baseline (speedup 1.0000x reference)
#include <cuda_runtime.h>
#include <cuda_bf16.h>
#include <cstdint>
#include <cstddef>

#define BB 32
#define TT 2048
#define DD 512
#define UU 32
#define LOG2E 1.4426950408889634f

// Recursion chunking: 128 chunks of 16 steps, 16-step burn-in.
// Birkhoff: diam after 1 step <= 2*max|chain| ~ 0.7 (ln), tau ~ 0.31
// => residual ~ 0.7 * 0.31^15 ~ 2e-8, a per-row uniform shift which the
// final softmax cancels exactly.
#define CCH 128
#define LCH (TT / CCH)   // 16
#define HBI 16

__device__ float g_e2[BB * TT * UU];
__device__ float g_alpha[BB * TT * UU];
__device__ float g_beta[BB * TT * UU];

__device__ __forceinline__ float ex2a(float x) {
    float y; asm("ex2.approx.ftz.f32 %0, %1;" : "=f"(y) : "f"(x)); return y;
}
__device__ __forceinline__ float lg2a(float x) {
    float y; asm("lg2.approx.ftz.f32 %0, %1;" : "=f"(y) : "f"(x)); return y;
}
__device__ __forceinline__ unsigned long long pk2(float a, float b) {
    unsigned long long r; asm("mov.b64 %0, {%1, %2};" : "=l"(r) : "f"(a), "f"(b)); return r;
}
__device__ __forceinline__ void fma2(unsigned long long &acc, unsigned long long a, unsigned long long b) {
    asm("fma.rn.f32x2 %0, %1, %2, %0;" : "+l"(acc) : "l"(a), "l"(b));
}
__device__ __forceinline__ void add2(unsigned long long &a, unsigned long long b) {
    asm("add.rn.f32x2 %0, %0, %1;" : "+l"(a) : "l"(b));
}
__device__ __forceinline__ float2 up2(unsigned long long v) {
    float2 f; asm("mov.b64 {%0, %1}, %2;" : "=f"(f.x), "=f"(f.y) : "l"(v)); return f;
}
__device__ __forceinline__ uint32_t smem_u32(const void* p) {
    uint32_t a; asm("{ .reg .u64 t; cvta.to.shared.u64 t, %1; cvt.u32.u64 %0, t; }" : "=r"(a) : "l"(p));
    return a;
}

// ======================= HMMA GEMM (K1) ====================================
// e2 = LOG2E*(X @ kernel) + (bias [+bounds])*LOG2E via bf16 split:
//   D = Xh*Kh + Xl*Kh + Xh*Kl  (fp32 accum; dropped Xl*Kl ~ 2^-16 rel)
// R12 was L1-wavefront-bound (fragment LDG.64 touches 8 lines). Now X is
// streamed coalesced via warp-local cp.async.cg into a 4-stage smem ring
// (XOR-swizzled so fragment LDS.64s are 2-way = minimum).
#define GEMM_THREADS 256
#define NSTEP (DD / 16)        // 32 k-steps
#define NSTG 4                 // cp.async stages

// smem: BF [2][NSTEP][2][32] uint4 = 64KB, then X stages 4 x (128 rows x 64B)
#define SM_BF_BYTES (2 * NSTEP * 2 * 32 * 16)
#define SM_X_BASE   SM_BF_BYTES
#define SM_STAGE    (128 * 64)
#define SM_TOTAL    (SM_BF_BYTES + NSTG * SM_STAGE)

__device__ __forceinline__ uint32_t packbf(float x, float y) {
    __nv_bfloat162 t = __floats2bfloat162_rn(x, y);
    return *reinterpret_cast<uint32_t*>(&t);
}
__device__ __forceinline__ void splitbf(float x, float y, uint32_t &hi, uint32_t &lo) {
    __nv_bfloat162 h2 = __floats2bfloat162_rn(x, y);
    hi = *reinterpret_cast<uint32_t*>(&h2);
    float2 hf = __bfloat1622float2(h2);
    lo = packbf(x - hf.x, y - hf.y);
}

__device__ __forceinline__ void mma16816(
    float &d0, float &d1, float &d2, float &d3,
    uint32_t a0, uint32_t a1, uint32_t a2, uint32_t a3,
    uint32_t b0, uint32_t b1)
{
    asm volatile(
        "mma.sync.aligned.m16n8k16.row.col.f32.bf16.bf16.f32 "
        "{%0,%1,%2,%3}, {%4,%5,%6,%7}, {%8,%9}, {%0,%1,%2,%3};"
        : "+f"(d0), "+f"(d1), "+f"(d2), "+f"(d3)
        : "r"(a0), "r"(a1), "r"(a2), "r"(a3), "r"(b0), "r"(b1));
}

__device__ __forceinline__ void cpa16(uint32_t dst, const void* src) {
    asm volatile("cp.async.cg.shared.global [%0], [%1], 16;" :: "r"(dst), "l"(src));
}

// issue one stage: this warp stages its own 16 rows x 16 k (1KB), coalesced.
__device__ __forceinline__ void stage_issue(
    uint32_t xbase, int stg, int ks, const float* __restrict__ Xw, int lane)
{
    #pragma unroll
    for (int f = 0; f < 2; f++) {
        int idxl = f * 32 + lane;          // 0..63 float4s
        int r = idxl >> 2;                 // 0..15
        int fq = idxl & 3;                 // float4 within row
        uint32_t dst = xbase + (uint32_t)(stg * SM_STAGE) + (uint32_t)(r * 64)
                     + (uint32_t)(((fq ^ (r & 3)) << 4));
        cpa16(dst, Xw + (size_t)r * DD + ks * 16 + fq * 4);
    }
    asm volatile("cp.async.commit_group;" ::: "memory");
}

__global__ void __launch_bounds__(GEMM_THREADS, 2) gemm_mma_kernel(
    const float* __restrict__ X, const float* __restrict__ Kn,
    const float* __restrict__ bias, const float* __restrict__ lb,
    const float* __restrict__ rb)
{
    extern __shared__ __align__(16) char smem[];
    uint4* BFh = reinterpret_cast<uint4*>(smem);
    uint4* BFl = BFh + NSTEP * 2 * 32;

    const int tid = threadIdx.x;
    const int wid = tid >> 5;
    const int lane = tid & 31;
    const int qrow = lane >> 2;          // 0..7
    const int qcol = lane & 3;           // 0..3
    const size_t rowBase = (size_t)blockIdx.x * 128 + wid * 16;
    const float* Xw = X + rowBase * DD;
    // warp-local X stage base (this warp's 16 rows live at wid*1KB)
    const uint32_t xbase = smem_u32(smem) + SM_X_BASE + (uint32_t)(wid * 1024);

    // ---- stage B fragments (once per CTA); kernel 64KB, L2-resident ----
    for (int idx = tid; idx < NSTEP * 2 * 32; idx += GEMM_THREADS) {
        int l = idx & 31;
        int kq = idx >> 5;               // kstep*2 + q
        int k = (kq >> 1) * 16 + (l & 3) * 2 + (kq & 1) * 8;
        uint32_t h[4], lo[4];
        #pragma unroll
        for (int nt = 0; nt < 4; nt++) {
            int u = nt * 8 + (l >> 2);
            float x0 = __ldg(Kn + (size_t)k * UU + u) * LOG2E;
            float x1 = __ldg(Kn + (size_t)(k + 1) * UU + u) * LOG2E;
            splitbf(x0, x1, h[nt], lo[nt]);
        }
        BFh[idx] = make_uint4(h[0], h[1], h[2], h[3]);
        BFl[idx] = make_uint4(lo[0], lo[1], lo[2], lo[3]);
    }

    // prologue: stages 0..2 in flight (warp-local, no CTA barrier needed for X)
    stage_issue(xbase, 0, 0, Xw, lane);
    stage_issue(xbase, 1, 1, Xw, lane);
    stage_issue(xbase, 2, 2, Xw, lane);
    __syncthreads();   // BF visibility (also orders X stage issues, harmless)

    float acc[4][4];
    #pragma unroll
    for (int nt = 0; nt < 4; nt++)
        #pragma unroll
        for (int j = 0; j < 4; j++) acc[nt][j] = 0.f;

    // fragment LDS offsets (r&3 identical for qrow and qrow+8)
    const uint32_t s0 = (uint32_t)(((qcol >> 1) ^ (qrow & 3)) << 4) + (uint32_t)((qcol & 1) << 3);
    const uint32_t s1 = (uint32_t)((((qcol >> 1) + 2) ^ (qrow & 3)) << 4) + (uint32_t)((qcol & 1) << 3);
    const uint32_t ro0 = (uint32_t)(qrow * 64);
    const uint32_t ro1 = (uint32_t)((qrow + 8) * 64);

    #pragma unroll 4
    for (int ks = 0; ks < NSTEP; ks++) {
        if (ks + 3 < NSTEP) {
            stage_issue(xbase, (ks + 3) & (NSTG - 1), ks + 3, Xw, lane);
        } else {
            asm volatile("cp.async.commit_group;" ::: "memory");  // keep count uniform
        }
        asm volatile("cp.async.wait_group 3;" ::: "memory");
        __syncwarp();

        const uint32_t sb = xbase + (uint32_t)((ks & (NSTG - 1)) * SM_STAGE);
        float2 xv[4];
        asm volatile("ld.shared.v2.f32 {%0,%1}, [%2];" : "=f"(xv[0].x), "=f"(xv[0].y) : "r"(sb + ro0 + s0));
        asm volatile("ld.shared.v2.f32 {%0,%1}, [%2];" : "=f"(xv[1].x), "=f"(xv[1].y) : "r"(sb + ro1 + s0));
        asm volatile("ld.shared.v2.f32 {%0,%1}, [%2];" : "=f"(xv[2].x), "=f"(xv[2].y) : "r"(sb + ro0 + s1));
        asm volatile("ld.shared.v2.f32 {%0,%1}, [%2];" : "=f"(xv[3].x), "=f"(xv[3].y) : "r"(sb + ro1 + s1));

        uint32_t ah[4], al[4];
        #pragma unroll
        for (int j = 0; j < 4; j++) splitbf(xv[j].x, xv[j].y, ah[j], al[j]);

        uint4 bh0 = BFh[(ks * 2 + 0) * 32 + lane];
        uint4 bh1 = BFh[(ks * 2 + 1) * 32 + lane];
        uint4 bl0 = BFl[(ks * 2 + 0) * 32 + lane];
        uint4 bl1 = BFl[(ks * 2 + 1) * 32 + lane];

        const uint32_t* b0h = &bh0.x; const uint32_t* b1h = &bh1.x;
        const uint32_t* b0l = &bl0.x; const uint32_t* b1l = &bl1.x;
        #pragma unroll
        for (int nt = 0; nt < 4; nt++) {
            mma16816(acc[nt][0], acc[nt][1], acc[nt][2], acc[nt][3],
                     ah[0], ah[1], ah[2], ah[3], b0h[nt], b1h[nt]);
            mma16816(acc[nt][0], acc[nt][1], acc[nt][2], acc[nt][3],
                     al[0], al[1], al[2], al[3], b0h[nt], b1h[nt]);
            mma16816(acc[nt][0], acc[nt][1], acc[nt][2], acc[nt][3],
                     ah[0], ah[1], ah[2], ah[3], b0l[nt], b1l[nt]);
        }
    }

    // ---- epilogue ----
    size_t row0 = rowBase + qrow;
    size_t row1 = row0 + 8;
    int t0 = (int)(row0 & (TT - 1)), t1 = (int)(row1 & (TT - 1));
    float f00 = (t0 == 0) ? 1.f : 0.f, f01 = (t0 == TT - 1) ? 1.f : 0.f;
    float f10 = (t1 == 0) ? 1.f : 0.f, f11 = (t1 == TT - 1) ? 1.f : 0.f;
    #pragma unroll
    for (int nt = 0; nt < 4; nt++) {
        int col = nt * 8 + qcol * 2;
        float bc0 = __ldg(bias + col),     bc1 = __ldg(bias + col + 1);
        float lc0 = __ldg(lb + col),       lc1 = __ldg(lb + col + 1);
        float rc0 = __ldg(rb + col),       rc1 = __ldg(rb + col + 1);
        float2 o0, o1;
        o0.x = acc[nt][0] + (bc0 + f00 * lc0 + f01 * rc0) * LOG2E;
        o0.y = acc[nt][1] + (bc1 + f00 * lc1 + f01 * rc1) * LOG2E;
        o1.x = acc[nt][2] + (bc0 + f10 * lc0 + f11 * rc0) * LOG2E;
        o1.y = acc[nt][3] + (bc1 + f10 * lc1 + f11 * rc1) * LOG2E;
        *reinterpret_cast<float2*>(g_e2 + row0 * UU + col) = o0;
        *reinterpret_cast<float2*>(g_e2 + row1 * UU + col) = o1;
    }
}

// ======================= K2: chunked recursion =============================
template <bool STORE>
__device__ __forceinline__ void rstep(
    float &eslot, const float &enext, float &d, int tc, int lpref,
    const float* __restrict__ ep, float* __restrict__ op, long stepE,
    const unsigned long long (&w2)[16], float (*pbuf)[32],
    int lane, float &carry, float &n1)
{
    float p = ex2a(carry + d);
    pbuf[tc & 1][lane] = p;
    if (tc + 4 < lpref) eslot = __ldg(ep + (long)(tc + 4) * stepE);
    d = n1 - enext;
    __syncwarp();
    const ulonglong2* pb = reinterpret_cast<const ulonglong2*>(pbuf[tc & 1]);
    unsigned long long a0 = 0ull, a1 = 0ull, a2 = 0ull, a3 = 0ull;
    #pragma unroll
    for (int i = 0; i < 4; i++) {
        ulonglong2 qa = pb[2 * i];
        ulonglong2 qb = pb[2 * i + 1];
        fma2(a0, qa.x, w2[4 * i + 0]);
        fma2(a1, qa.y, w2[4 * i + 1]);
        fma2(a2, qb.x, w2[4 * i + 2]);
        fma2(a3, qb.y, w2[4 * i + 3]);
    }
    add2(a0, a1); add2(a2, a3); add2(a0, a2);
    float2 s = up2(a0);
    carry = lg2a(s.x + s.y);
    if (STORE) op[(long)tc * stepE] = carry;
    n1 = -__shfl_sync(0xffffffffu, carry, 0);
}

__global__ void __launch_bounds__(32) crf_rec_kernel(const float* __restrict__ chain)
{
    __shared__ __align__(16) float pbuf[2][32];
    const int lane = threadIdx.x;
    const int c   = blockIdx.x & (CCH - 1);
    const int bd  = blockIdx.x >> 7;       // CCH == 128
    const int b   = bd & 31;
    const int dir = bd >> 5;

    unsigned long long w2[16];
    #pragma unroll
    for (int j = 0; j < 16; j++) {
        float wa = ex2a(-LOG2E * __ldg(chain + (2 * j) * UU + lane));
        float wb = ex2a(-LOG2E * __ldg(chain + (2 * j + 1) * UU + lane));
        w2[j] = pk2(wa, wb);
    }

    const long stepE = dir ? -(long)UU : (long)UU;
    const size_t base = (size_t)b * TT * UU + (dir ? (size_t)(TT - 1) * UU : 0) + lane;
    const float* ep = g_e2 + base;
    float* op = (dir ? g_beta : g_alpha) + base;

    const int l0 = c * LCH;
    const int h  = (c == 0) ? 0 : HBI;
    const int ls = l0 - h;
    const int lend = l0 + LCH;

    float e0  = __ldg(ep + (long)(ls + 0) * stepE);
    float e1  = __ldg(ep + (long)(ls + 1) * stepE);
    float e2v = __ldg(ep + (long)(ls + 2) * stepE);
    float e3  = __ldg(ep + (long)(ls + 3) * stepE);

    float carry = 0.f, n1 = 0.f;
    float d = -e0;

    for (int t = ls; t < l0; t += 4) {
        rstep<false>(e0,  e1,  d, t + 0, lend, ep, op, stepE, w2, pbuf, lane, carry, n1);
        rstep<false>(e1,  e2v, d, t + 1, lend, ep, op, stepE, w2, pbuf, lane, carry, n1);
        rstep<false>(e2v, e3,  d, t + 2, lend, ep, op, stepE, w2, pbuf, lane, carry, n1);
        rstep<false>(e3,  e0,  d, t + 3, lend, ep, op, stepE, w2, pbuf, lane, carry, n1);
    }
    for (int t = l0; t < lend; t += 4) {
        rstep<true>(e0,  e1,  d, t + 0, lend, ep, op, stepE, w2, pbuf, lane, carry, n1);
        rstep<true>(e1,  e2v, d, t + 1, lend, ep, op, stepE, w2, pbuf, lane, carry, n1);
        rstep<true>(e2v, e3,  d, t + 2, lend, ep, op, stepE, w2, pbuf, lane, carry, n1);
        rstep<true>(e3,  e0,  d, t + 3, lend, ep, op, stepE, w2, pbuf, lane, carry, n1);
    }
}

// ======================= K3: margin + softmax ==============================
__global__ void __launch_bounds__(256) crf_soft_kernel(float* __restrict__ out)
{
    const int tid = threadIdx.x;
    const int u0 = (tid & 7) * 4;
    const size_t row = (size_t)blockIdx.x * 32 + (tid >> 3);
    const int t = (int)(row & (TT - 1));

    float4 z = make_float4(0.f, 0.f, 0.f, 0.f);
    float4 a  = (t > 0)      ? *reinterpret_cast<const float4*>(g_alpha + (row - 1) * UU + u0) : z;
    float4 e  = *reinterpret_cast<const float4*>(g_e2 + row * UU + u0);
    float4 bt = (t < TT - 1) ? *reinterpret_cast<const float4*>(g_beta + (row + 1) * UU + u0) : z;

    float4 m;
    m.x = -(a.x + e.x + bt.x); m.y = -(a.y + e.y + bt.y);
    m.z = -(a.z + e.z + bt.z); m.w = -(a.w + e.w + bt.w);

    float mx = fmaxf(fmaxf(m.x, m.y), fmaxf(m.z, m.w));
    #pragma unroll
    for (int o = 4; o > 0; o >>= 1) mx = fmaxf(mx, __shfl_xor_sync(0xffffffffu, mx, o));

    float4 p;
    p.x = ex2a(m.x - mx); p.y = ex2a(m.y - mx);
    p.z = ex2a(m.z - mx); p.w = ex2a(m.w - mx);
    float s = (p.x + p.y) + (p.z + p.w);
    #pragma unroll
    for (int o = 4; o > 0; o >>= 1) s += __shfl_xor_sync(0xffffffffu, s, o);

    float inv = __fdividef(1.f, s);
    p.x *= inv; p.y *= inv; p.z *= inv; p.w *= inv;
    *reinterpret_cast<float4*>(out + row * UU + u0) = p;
}

// ===========================================================================
extern "C" void kernel_launch(void* const* d_in, const int* in_sizes, int n_in,
                              void* d_out, int out_size)
{
    const float* X     = (const float*)d_in[0];
    const float* Kn    = (const float*)d_in[1];
    const float* chain = (const float*)d_in[2];
    const float* bias  = (const float*)d_in[3];
    const float* lb    = (const float*)d_in[4];
    const float* rb    = (const float*)d_in[5];
    float* out = (float*)d_out;

    cudaFuncSetAttribute(gemm_mma_kernel,
                         cudaFuncAttributeMaxDynamicSharedMemorySize, SM_TOTAL);

    gemm_mma_kernel<<<(BB * TT) / 128, GEMM_THREADS, SM_TOTAL>>>(X, Kn, bias, lb, rb);
    crf_rec_kernel<<<64 * CCH, 32>>>(chain);
    crf_soft_kernel<<<(BB * TT) / 32, 256>>>(out);
}